// round 17
// baseline (speedup 1.0000x reference)
#include <cuda_runtime.h>
#include <cuda_bf16.h>
#include <cstdint>
#include <math.h>

#define BATCH 256
#define SRCLEN 120
#define TGTLEN 24
#define DIN 216
#define HID 1024
#define KPAD 256

#define KC 128                // K per pipeline chunk
#define NCHUNK_H (HID / KC)   // 8
#define NCHUNK_X (KPAD / KC)  // 2
#define NCHUNK (NCHUNK_H + NCHUNK_X)   // 10
#define NCTA 128              // persistent grid size (32 x 4)

#define AROW 272              // smem row stride bytes (256B data + 16B pad)
#define OFF_AHI 0
#define OFF_ALO 34816
#define OFF_BHI 69632
#define OFF_BLO 87040
#define STAGE_BYTES 104448
#define SMEM_TOTAL (2 * STAGE_BYTES)   // 208896

// ---------------------------------------------------------------------------
// Static device scratch (no runtime allocation allowed)
// ---------------------------------------------------------------------------
__device__ __nv_bfloat16 g_Whh_hi[4096 * HID];
__device__ __nv_bfloat16 g_Whh_lo[4096 * HID];
__device__ __nv_bfloat16 g_Wih_hi[4096 * KPAD];
__device__ __nv_bfloat16 g_Wih_lo[4096 * KPAD];
__device__ __nv_bfloat16 g_Xsrc_hi[SRCLEN * BATCH * KPAD];
__device__ __nv_bfloat16 g_Xsrc_lo[SRCLEN * BATCH * KPAD];
__device__ __nv_bfloat16 g_xdec_hi[BATCH * KPAD];
__device__ __nv_bfloat16 g_xdec_lo[BATCH * KPAD];
__device__ __nv_bfloat16 g_hhi[2][BATCH * HID];
__device__ __nv_bfloat16 g_hlo[2][BATCH * HID];
__device__ float g_hf[BATCH * HID];
__device__ float g_c[BATCH * HID];
__device__ float g_bsum[4096];        // b_ih + b_hh pre-summed
__device__ unsigned g_sync_cnt;       // grid-barrier monotonic counter

// ---------------------------------------------------------------------------
// sm_80-safe PTX helpers
// ---------------------------------------------------------------------------
__device__ __forceinline__ uint32_t smem_u32(const void* p) {
    return (uint32_t)__cvta_generic_to_shared(p);
}
__device__ __forceinline__ void cp_async16(uint32_t saddr, const void* gaddr) {
    asm volatile("cp.async.cg.shared.global [%0], [%1], 16;" ::
                 "r"(saddr), "l"(gaddr));
}
__device__ __forceinline__ void cp_commit() {
    asm volatile("cp.async.commit_group;");
}
__device__ __forceinline__ void cp_wait0() {
    asm volatile("cp.async.wait_group 0;");
}
__device__ __forceinline__ void ldmx4(uint32_t addr, uint32_t* r) {
    asm volatile("ldmatrix.sync.aligned.m8n8.x4.shared.b16 {%0,%1,%2,%3}, [%4];"
                 : "=r"(r[0]), "=r"(r[1]), "=r"(r[2]), "=r"(r[3]) : "r"(addr));
}
__device__ __forceinline__ void mma_bf16(float* d, const uint32_t* a,
                                         uint32_t b0, uint32_t b1) {
    asm volatile(
        "mma.sync.aligned.m16n8k16.row.col.f32.bf16.bf16.f32 "
        "{%0,%1,%2,%3}, {%4,%5,%6,%7}, {%8,%9}, {%0,%1,%2,%3};"
        : "+f"(d[0]), "+f"(d[1]), "+f"(d[2]), "+f"(d[3])
        : "r"(a[0]), "r"(a[1]), "r"(a[2]), "r"(a[3]), "r"(b0), "r"(b1));
}

// ===========================================================================
// UNIFIED PERSISTENT KERNEL: 120 encoder + 24 decoder LSTM steps with fused
// output projection + feedback. Grid (32,4)=128 CTAs, 1/SM, co-resident.
// ===========================================================================
__global__ __launch_bounds__(512) void lstm_persistent(
    float* __restrict__ out,
    const float* __restrict__ W_out, const float* __restrict__ b_out)
{
    extern __shared__ __align__(128) char sm[];
    const uint32_t smb = smem_u32(sm);

    const int tid = threadIdx.x;
    const int wid = tid >> 5;
    const int lane = tid & 31;
    const int j0 = blockIdx.x * 32;
    const int b0 = blockIdx.y * 64;
    const int cid = blockIdx.y * 32 + blockIdx.x;   // 0..127

    const int moff = (wid & 3) * 32;
    const int noff = (wid >> 2) * 16;
    const int rot = ((wid >> 2) + (wid & 3) * 4) & 7;

    const __nv_bfloat16* xlast_hi = g_Xsrc_hi + (size_t)(SRCLEN - 1) * BATCH * KPAD;
    const __nv_bfloat16* xlast_lo = g_Xsrc_lo + (size_t)(SRCLEN - 1) * BATCH * KPAD;

    int epoch = 0;
    auto grid_barrier = [&]() {
        __syncthreads();                 // all CTA threads' writes done
        epoch++;
        if (tid == 0) {
            __threadfence();
            atomicAdd(&g_sync_cnt, 1u);
            const unsigned target = (unsigned)NCTA * (unsigned)epoch;
            while (atomicAdd(&g_sync_cnt, 0u) < target) {}
            __threadfence();
        }
        __syncthreads();
    };

    // ---- loaders ----
    auto issue_A = [&](int chunk, int stage) {   // weights only
        const __nv_bfloat16 *Ahi, *Alo;
        int ks, k0;
        if (chunk < NCHUNK_H) { Ahi = g_Whh_hi; Alo = g_Whh_lo; ks = HID; k0 = chunk * KC; }
        else { Ahi = g_Wih_hi; Alo = g_Wih_lo; ks = KPAD; k0 = (chunk - NCHUNK_H) * KC; }
        const uint32_t sbase = smb + stage * STAGE_BYTES;
#pragma unroll
        for (int i = 0; i < 8; i++) {
            int o = tid + i * 512;
            int m = o & 2047;
            int r = m >> 4, c16 = m & 15;
            int grow = ((r >> 5) * HID) + j0 + (r & 31);
            const __nv_bfloat16* g = ((o < 2048) ? Ahi : Alo)
                                     + (size_t)grow * ks + k0 + c16 * 8;
            cp_async16(sbase + ((o < 2048) ? OFF_AHI : OFF_ALO) + r * AROW + c16 * 16, g);
        }
    };
    // B: h from hbuf; x from (xh, xl)
    auto issue_B = [&](int chunk, int stage, int hbuf,
                       const __nv_bfloat16* xh, const __nv_bfloat16* xl) {
        const __nv_bfloat16 *Bhi, *Blo;
        int ks, k0;
        if (chunk < NCHUNK_H) {
            Bhi = g_hhi[hbuf]; Blo = g_hlo[hbuf]; ks = HID; k0 = chunk * KC;
        } else {
            Bhi = xh; Blo = xl; ks = KPAD; k0 = (chunk - NCHUNK_H) * KC;
        }
        const uint32_t sbase = smb + stage * STAGE_BYTES;
#pragma unroll
        for (int i = 0; i < 4; i++) {
            int o = tid + i * 512;
            int mm = o & 1023;
            int r = mm >> 4, c16 = mm & 15;
            const __nv_bfloat16* g = ((o < 1024) ? Bhi : Blo)
                                     + (size_t)(b0 + r) * ks + k0 + c16 * 8;
            cp_async16(sbase + ((o < 1024) ? OFF_BHI : OFF_BLO) + r * AROW + c16 * 16, g);
        }
    };

    float acc0[2][2][4], acc1[2][2][4], acc2[2][2][4];

    auto zero_acc = [&]() {
#pragma unroll
        for (int t = 0; t < 2; t++)
#pragma unroll
            for (int q = 0; q < 2; q++)
#pragma unroll
                for (int i = 0; i < 4; i++) {
                    acc0[t][q][i] = 0.f; acc1[t][q][i] = 0.f; acc2[t][q][i] = 0.f;
                }
    };

    auto compute_range = [&](int stage, int g_lo, int g_hi) {
        const uint32_t ab = smb + stage * STAGE_BYTES;
#pragma unroll
        for (int g = g_lo; g < g_hi; g++) {
            const int kk = ((g + rot) & 7) * 16;
            const int col = kk + ((lane >> 4) << 3);
            uint32_t a_hi[2][4], a_lo[2][4];
#pragma unroll
            for (int t = 0; t < 2; t++) {
                int row = moff + t * 16 + (lane & 15);
                ldmx4(ab + OFF_AHI + row * AROW + col * 2, a_hi[t]);
                ldmx4(ab + OFF_ALO + row * AROW + col * 2, a_lo[t]);
            }
            uint32_t b_hi[4], b_lo[4];
            {
                int row = noff + (lane & 15);
                ldmx4(ab + OFF_BHI + row * AROW + col * 2, b_hi);
                ldmx4(ab + OFF_BLO + row * AROW + col * 2, b_lo);
            }
#pragma unroll
            for (int t = 0; t < 2; t++)
#pragma unroll
                for (int q = 0; q < 2; q++) {
                    mma_bf16(acc0[t][q], a_hi[t], b_hi[q], b_hi[q + 2]);
                    mma_bf16(acc1[t][q], a_hi[t], b_lo[q], b_lo[q + 2]);
                    mma_bf16(acc2[t][q], a_lo[t], b_hi[q], b_hi[q + 2]);
                }
        }
    };

    // Dsm in STAGE-1 A region (stage 0 holds the cross-boundary A prefetch)
    float* Dsm = reinterpret_cast<float*>(sm + STAGE_BYTES);

    auto mainloop = [&](int hbuf, const __nv_bfloat16* xh, const __nv_bfloat16* xl) {
        for (int i = 0; i < NCHUNK; i++) {
            cp_wait0();
            __syncthreads();
            compute_range(i & 1, 0, 2);
            if (i + 1 < NCHUNK) {
                issue_A(i + 1, (i + 1) & 1);
                issue_B(i + 1, (i + 1) & 1, hbuf, xh, xl);
                cp_commit();
            }
            compute_range(i & 1, 2, 8);
        }
        __syncthreads();                 // drain stage-1 readers (chunk 9)
    };

    // epilogue: frags -> Dsm -> pointwise; optionally write fp32 h
    auto epilogue = [&](__nv_bfloat16* h_hi_out, __nv_bfloat16* h_lo_out, bool write_hf) {
#pragma unroll
        for (int t = 0; t < 2; t++)
#pragma unroll
            for (int q = 0; q < 2; q++) {
                int r0 = moff + t * 16 + (lane >> 2);
                int c0 = noff + q * 8 + (lane & 3) * 2;
#pragma unroll
                for (int i = 0; i < 4; i++) {
                    float v = acc0[t][q][i] + acc1[t][q][i] + acc2[t][q][i];
                    Dsm[(r0 + (i >> 1) * 8) * 68 + c0 + (i & 1)] = v;
                }
            }
        __syncthreads();
#pragma unroll
        for (int i = 0; i < 4; i++) {
            int id = tid + i * 512;
            int bb = id >> 5;
            int jj = id & 31;
            int b = b0 + bb;
            int jg = j0 + jj;
            float gi = Dsm[(0  + jj) * 68 + bb] + g_bsum[jg];
            float gf = Dsm[(32 + jj) * 68 + bb] + g_bsum[HID + jg];
            float gg = Dsm[(64 + jj) * 68 + bb] + g_bsum[2*HID + jg];
            float go = Dsm[(96 + jj) * 68 + bb] + g_bsum[3*HID + jg];
            float iv = 1.f / (1.f + expf(-gi));
            float fv = 1.f / (1.f + expf(-gf));
            float gv = tanhf(gg);
            float ov = 1.f / (1.f + expf(-go));
            size_t idx = (size_t)b * HID + jg;
            float cn = fv * g_c[idx] + iv * gv;
            g_c[idx] = cn;
            float hv = ov * tanhf(cn);
            if (write_hf) g_hf[idx] = hv;
            __nv_bfloat16 hh = __float2bfloat16(hv);
            h_hi_out[idx] = hh;
            h_lo_out[idx] = __float2bfloat16(hv - __bfloat162float(hh));
        }
    };

    // fused output projection: warp handles (batch, 27-d chunk)
    auto out_proj_fused = [&](int t, bool feed) {
        const int dc = cid & 7;                      // d-chunk (27 d's)
        const int bb = ((cid >> 3) << 4) + wid;      // batch 0..255
        const float4* h4p = reinterpret_cast<const float4*>(g_hf + (size_t)bb * HID);
        float4 h4[8];
#pragma unroll
        for (int i = 0; i < 8; i++) h4[i] = h4p[lane + i * 32];
        for (int dd = 0; dd < 27; dd++) {
            int d = dc * 27 + dd;
            const float4* w4p = reinterpret_cast<const float4*>(W_out + (size_t)d * HID);
            float dot = 0.f;
#pragma unroll
            for (int i = 0; i < 8; i++) {
                float4 w = w4p[lane + i * 32];
                dot += h4[i].x * w.x + h4[i].y * w.y + h4[i].z * w.z + h4[i].w * w.w;
            }
#pragma unroll
            for (int off = 16; off; off >>= 1)
                dot += __shfl_xor_sync(0xffffffffu, dot, off);
            if (lane == 0) {
                float v = dot + b_out[d];
                out[((size_t)bb * TGTLEN + t) * DIN + d] = v;
                if (feed) {
                    __nv_bfloat16 hh = __float2bfloat16(v);
                    g_xdec_hi[(size_t)bb * KPAD + d] = hh;
                    g_xdec_lo[(size_t)bb * KPAD + d] =
                        __float2bfloat16(v - __bfloat162float(hh));
                }
            }
        }
    };

    // ================= ENCODER =================
    issue_A(0, 0);
    issue_B(0, 0, 0, g_Xsrc_hi, g_Xsrc_lo);
    cp_commit();

    for (int s = 0; s < SRCLEN; s++) {
        const __nv_bfloat16* xh = g_Xsrc_hi + (size_t)s * BATCH * KPAD;
        const __nv_bfloat16* xl = g_Xsrc_lo + (size_t)s * BATCH * KPAD;
        zero_acc();
        mainloop(s & 1, xh, xl);
        issue_A(0, 0);           // cross-boundary weight prefetch (stage 0 drained)
        cp_commit();
        epilogue(g_hhi[1 - (s & 1)], g_hlo[1 - (s & 1)], false);
        grid_barrier();          // publish h (syncthreads-before-arrive inside)
        if (s + 1 < SRCLEN) {
            issue_B(0, 0, (s + 1) & 1,
                    g_Xsrc_hi + (size_t)(s + 1) * BATCH * KPAD,
                    g_Xsrc_lo + (size_t)(s + 1) * BATCH * KPAD);
            cp_commit();
        }
    }

    // ================= DECODER =================
    // After encoder: h in buf 0. First decoder x = last src frame.
    issue_B(0, 0, 0, xlast_hi, xlast_lo);
    cp_commit();

    for (int t = 0; t < TGTLEN; t++) {
        const __nv_bfloat16* xh = (t == 0) ? xlast_hi : g_xdec_hi;
        const __nv_bfloat16* xl = (t == 0) ? xlast_lo : g_xdec_lo;
        const bool feed = (t + 1 < TGTLEN);
        zero_acc();
        mainloop(t & 1, xh, xl);
        if (feed) { issue_A(0, 0); cp_commit(); }
        epilogue(g_hhi[1 - (t & 1)], g_hlo[1 - (t & 1)], true);
        grid_barrier();          // publish hf + h
        if (feed) {
            issue_B(0, 0, (t + 1) & 1, g_xdec_hi, g_xdec_lo);  // h rows (chunk 0)
            cp_commit();
        }
        out_proj_fused(t, feed);
        if (feed) grid_barrier();   // publish xd before chunk-8 prefetch (iter 7)
    }
}

// ---------------------------------------------------------------------------
// Conversion kernels
// ---------------------------------------------------------------------------
__global__ void split_mat_kernel(const float* __restrict__ src,
                                 __nv_bfloat16* __restrict__ hi,
                                 __nv_bfloat16* __restrict__ lo, int n) {
    int i = blockIdx.x * blockDim.x + threadIdx.x;
    if (i < n) {
        float v = src[i];
        __nv_bfloat16 h = __float2bfloat16(v);
        hi[i] = h;
        lo[i] = __float2bfloat16(v - __bfloat162float(h));
    }
}

__global__ void split_pad_kernel(const float* __restrict__ src, int srcStride, int srcK,
                                 __nv_bfloat16* __restrict__ hi,
                                 __nv_bfloat16* __restrict__ lo, int rows, int dstK) {
    int i = blockIdx.x * blockDim.x + threadIdx.x;
    if (i < rows * dstK) {
        int r = i / dstK, k = i % dstK;
        float v = (k < srcK) ? src[(size_t)r * srcStride + k] : 0.f;
        __nv_bfloat16 h = __float2bfloat16(v);
        hi[i] = h;
        lo[i] = __float2bfloat16(v - __bfloat162float(h));
    }
}

__global__ void split_src_kernel(const float* __restrict__ src,
                                 __nv_bfloat16* __restrict__ hi,
                                 __nv_bfloat16* __restrict__ lo) {
    int i = blockIdx.x * blockDim.x + threadIdx.x;
    if (i < SRCLEN * BATCH * KPAD) {
        int k = i & (KPAD - 1);
        int sb = i >> 8;
        int b = sb & (BATCH - 1);
        int s = sb >> 8;
        float v = (k < DIN) ? src[((size_t)b * SRCLEN + s) * DIN + k] : 0.f;
        __nv_bfloat16 h = __float2bfloat16(v);
        hi[i] = h;
        lo[i] = __float2bfloat16(v - __bfloat162float(h));
    }
}

__global__ void bias_sum_kernel(const float* __restrict__ b_ih,
                                const float* __restrict__ b_hh,
                                float* __restrict__ bsum) {
    int i = blockIdx.x * blockDim.x + threadIdx.x;
    if (i < 4096) bsum[i] = b_ih[i] + b_hh[i];
}

// ---------------------------------------------------------------------------
extern "C" void kernel_launch(void* const* d_in, const int* in_sizes, int n_in,
                              void* d_out, int out_size)
{
    const float* src   = (const float*)d_in[0];
    const float* W_ih  = (const float*)d_in[2];
    const float* W_hh  = (const float*)d_in[3];
    const float* b_ih  = (const float*)d_in[4];
    const float* b_hh  = (const float*)d_in[5];
    const float* W_out = (const float*)d_in[6];
    const float* b_out = (const float*)d_in[7];
    float* out = (float*)d_out;

    static bool attr_set = false;
    if (!attr_set) {
        cudaFuncSetAttribute(lstm_persistent,
                             cudaFuncAttributeMaxDynamicSharedMemorySize, SMEM_TOTAL);
        attr_set = true;
    }

    __nv_bfloat16 *Whh_hi, *Wih_hi, *Xs_hi, *Xs_lo, *xd_hi, *xd_lo, *hhi, *hlo;
    __nv_bfloat16 *Whh_lo, *Wih_lo;
    float *cc, *bsum;
    unsigned* sync_cnt;
    cudaGetSymbolAddress((void**)&Whh_hi, g_Whh_hi);
    cudaGetSymbolAddress((void**)&Whh_lo, g_Whh_lo);
    cudaGetSymbolAddress((void**)&Wih_hi, g_Wih_hi);
    cudaGetSymbolAddress((void**)&Wih_lo, g_Wih_lo);
    cudaGetSymbolAddress((void**)&Xs_hi, g_Xsrc_hi);
    cudaGetSymbolAddress((void**)&Xs_lo, g_Xsrc_lo);
    cudaGetSymbolAddress((void**)&xd_hi, g_xdec_hi);
    cudaGetSymbolAddress((void**)&xd_lo, g_xdec_lo);
    cudaGetSymbolAddress((void**)&hhi, g_hhi);
    cudaGetSymbolAddress((void**)&hlo, g_hlo);
    cudaGetSymbolAddress((void**)&cc, g_c);
    cudaGetSymbolAddress((void**)&bsum, g_bsum);
    cudaGetSymbolAddress((void**)&sync_cnt, g_sync_cnt);

    cudaMemsetAsync(hhi, 0, (size_t)BATCH * HID * sizeof(__nv_bfloat16));
    cudaMemsetAsync(hlo, 0, (size_t)BATCH * HID * sizeof(__nv_bfloat16));
    cudaMemsetAsync(cc, 0, (size_t)BATCH * HID * sizeof(float));
    cudaMemsetAsync(xd_hi, 0, (size_t)BATCH * KPAD * sizeof(__nv_bfloat16));
    cudaMemsetAsync(xd_lo, 0, (size_t)BATCH * KPAD * sizeof(__nv_bfloat16));
    cudaMemsetAsync(sync_cnt, 0, sizeof(unsigned));

    {
        int n = 4096 * HID;
        split_mat_kernel<<<(n + 255) / 256, 256>>>(W_hh, Whh_hi, Whh_lo, n);
        split_pad_kernel<<<(4096 * KPAD + 255) / 256, 256>>>(W_ih, DIN, DIN,
                                                             Wih_hi, Wih_lo, 4096, KPAD);
        int m = SRCLEN * BATCH * KPAD;
        split_src_kernel<<<(m + 255) / 256, 256>>>(src, Xs_hi, Xs_lo);
        bias_sum_kernel<<<16, 256>>>(b_ih, b_hh, bsum);
    }

    dim3 grid(32, 4);
    lstm_persistent<<<grid, 512, SMEM_TOTAL>>>(out, W_out, b_out);
}